// round 1
// baseline (speedup 1.0000x reference)
#include <cuda_runtime.h>
#include <cuda_bf16.h>

// Local2d: out[b,o,h,w] = sum_{i,kk,ll} weight[o,h,w,i,kk,ll] * xpad[b,i,h-1+kk,w-1+ll] + bias[o,h,w]
// B=64, C_IN=64, C_OUT=128, K=3, H=W=H_OUT=W_OUT=32, stride=1, pad=1.
//
// Formulated as 1024 independent GEMMs (one per (h,w)):
//   C[o,b] = W[o,k] * P[k,b],  M=128 (o), N=64 (b), Kred=576 (i*9+kk*3+ll)
// One block per location. Smem-tiled over Kred in chunks of 32.
// 128 threads, 8x8 register tile each (split as two float4 halves in both
// dims so warp LDS spans all 32 banks -> conflict-free operand fetch).

#define BB    64
#define CIN   64
#define COUT  128
#define KTOT  576
#define KC    32
#define NCHUNK (KTOT / KC)

__global__ __launch_bounds__(128, 4)
void local2d_kernel(const float* __restrict__ x,
                    const float* __restrict__ weight,
                    const float* __restrict__ bias,
                    float* __restrict__ out)
{
    // Ws: [k][o] with pad (stride 132 keeps float4 alignment: 132*4 % 16 == 0)
    // Ps: [k][b] with pad (stride 68,  68*4 % 16 == 0)
    __shared__ float Ws[KC][132];
    __shared__ float Ps[KC][68];

    const int tid = threadIdx.x;
    const int row = tid >> 3;   // 0..15 -> o-groups
    const int col = tid & 7;    // 0..7  -> b-groups
    const int loc = blockIdx.x; // 0..1023 : (h,w)
    const int h = loc >> 5;
    const int w = loc & 31;

    float acc[8][8];
#pragma unroll
    for (int i = 0; i < 8; i++)
#pragma unroll
        for (int j = 0; j < 8; j++) acc[i][j] = 0.f;

    // weight[o][h][w][k] : offset o*1024*576 + loc*576 + k
    const float* wg = weight + (size_t)loc * KTOT;

    for (int c = 0; c < NCHUNK; c++) {
        const int k0 = c * KC;

        // ---- load W tile: 128 o x 32 k = 1024 float4 loads / 128 threads ----
        // lanes sweep k-quads fastest -> each warp reads 4 full contiguous
        // 128B rows of weight (perfectly coalesced LDG.128).
#pragma unroll
        for (int j = 0; j < 8; j++) {
            int idx = j * 128 + tid;          // 0..1023
            int o   = idx >> 3;               // 0..127
            int kq  = (idx & 7) << 2;         // 0,4,...,28
            float4 v = *(const float4*)(wg + (size_t)o * (1024 * KTOT) + k0 + kq);
            Ws[kq + 0][o] = v.x;
            Ws[kq + 1][o] = v.y;
            Ws[kq + 2][o] = v.z;
            Ws[kq + 3][o] = v.w;
        }

        // ---- load P tile: 32 k x 64 b (k fastest within a warp so lanes hit a
        // compact 3x3xCIN-neighborhood of x -> far fewer sectors than b-fast) --
#pragma unroll
        for (int j = 0; j < 16; j++) {
            int idx = j * 128 + tid;          // 0..2047
            int kk  = idx & 31;
            int b   = idx >> 5;               // 0..63
            int kg  = k0 + kk;
            int ci  = kg / 9;
            int r   = kg - ci * 9;
            int dh  = r / 3;
            int dw  = r - dh * 3;
            int hh  = h - 1 + dh;
            int ww2 = w - 1 + dw;
            float v = 0.f;
            if ((unsigned)hh < 32u && (unsigned)ww2 < 32u)
                v = x[((b * CIN + ci) << 10) + (hh << 5) + ww2];
            Ps[kk][b] = v;
        }
        __syncthreads();

        // ---- GEMM inner: 64 FFMA per k-step per thread, 4 LDS.128 ----
#pragma unroll 8
        for (int kk = 0; kk < KC; kk++) {
            float wv[8], pv[8];
            *(float4*)&wv[0] = *(const float4*)&Ws[kk][row * 4];
            *(float4*)&wv[4] = *(const float4*)&Ws[kk][64 + row * 4];
            *(float4*)&pv[0] = *(const float4*)&Ps[kk][col * 4];
            *(float4*)&pv[4] = *(const float4*)&Ps[kk][32 + col * 4];
#pragma unroll
            for (int io = 0; io < 8; io++)
#pragma unroll
                for (int ib = 0; ib < 8; ib++)
                    acc[io][ib] += wv[io] * pv[ib];
        }
        __syncthreads();
    }

    // ---- epilogue: out[b][o][h][w] ----
#pragma unroll
    for (int io = 0; io < 8; io++) {
        int o = (io < 4) ? (row * 4 + io) : (64 + row * 4 + (io - 4));
        float bv = bias[(o << 10) + loc];
#pragma unroll
        for (int ib = 0; ib < 8; ib++) {
            int b = (ib < 4) ? (col * 4 + ib) : (32 + col * 4 + (ib - 4));
            out[((b * COUT + o) << 10) + loc] = acc[io][ib] + bv;
        }
    }
}

extern "C" void kernel_launch(void* const* d_in, const int* in_sizes, int n_in,
                              void* d_out, int out_size) {
    const float* x      = (const float*)d_in[0];
    const float* weight = (const float*)d_in[1];
    const float* bias   = (const float*)d_in[2];
    float* out = (float*)d_out;
    local2d_kernel<<<1024, 128>>>(x, weight, bias, out);
}

// round 4
// speedup vs baseline: 1.0792x; 1.0792x over previous
#include <cuda_runtime.h>
#include <cuda_bf16.h>

// Local2d as 1024 independent GEMMs (one per (h,w)):
//   C[o,b] = W[o,k] * P[k,b],  M=128 (o), N=64 (b), Kred=576
// One block/location, 128 threads, 8x8 register tile per thread.
// Round 2: software pipeline — register prefetch of chunk c+1 overlapped with
// compute of chunk c, double-buffered smem, ONE barrier per chunk.

#define CIN    64
#define COUT   128
#define KTOT   576
#define KC     32
#define NCHUNK (KTOT / KC)
#define WS_STRIDE 132   // [k][o] rows, pad keeps 16B-aligned float4 loads
#define PS_STRIDE 68    // [k][b] rows
#define SMEM_FLOATS (2 * KC * (WS_STRIDE + PS_STRIDE))
#define SMEM_BYTES  (SMEM_FLOATS * 4)

__device__ __forceinline__ void prefetch_tiles(
    const float* __restrict__ wg, const float* __restrict__ x,
    int k0, int h, int w, int tid, float4 wreg[8], float preg[16])
{
    // W: lanes sweep k-quads fastest -> each warp reads contiguous 128B rows
#pragma unroll
    for (int j = 0; j < 8; j++) {
        int idx = j * 128 + tid;
        int o   = idx >> 3;
        int kq  = (idx & 7) << 2;
        wreg[j] = *(const float4*)(wg + (size_t)o * (1024 * KTOT) + k0 + kq);
    }
    // P: gather from x with zero-pad at borders (k fastest for compact sectors)
#pragma unroll
    for (int j = 0; j < 16; j++) {
        int idx = j * 128 + tid;
        int kk  = idx & 31;
        int b   = idx >> 5;
        int kg  = k0 + kk;
        int ci  = kg / 9;
        int r   = kg - ci * 9;
        int dh  = r / 3;
        int dw  = r - dh * 3;
        int hh  = h - 1 + dh;
        int ww  = w - 1 + dw;
        float v = 0.f;
        if ((unsigned)hh < 32u && (unsigned)ww < 32u)
            v = x[((b * CIN + ci) << 10) + (hh << 5) + ww];
        preg[j] = v;
    }
}

__device__ __forceinline__ void store_tiles(
    float* __restrict__ Ws, float* __restrict__ Ps, int tid,
    const float4 wreg[8], const float preg[16])
{
#pragma unroll
    for (int j = 0; j < 8; j++) {
        int idx = j * 128 + tid;
        int o   = idx >> 3;
        int kq  = (idx & 7) << 2;
        Ws[(kq + 0) * WS_STRIDE + o] = wreg[j].x;
        Ws[(kq + 1) * WS_STRIDE + o] = wreg[j].y;
        Ws[(kq + 2) * WS_STRIDE + o] = wreg[j].z;
        Ws[(kq + 3) * WS_STRIDE + o] = wreg[j].w;
    }
#pragma unroll
    for (int j = 0; j < 16; j++) {
        int idx = j * 128 + tid;
        int kk  = idx & 31;
        int b   = idx >> 5;
        Ps[kk * PS_STRIDE + b] = preg[j];
    }
}

__global__ __launch_bounds__(128)
void local2d_kernel(const float* __restrict__ x,
                    const float* __restrict__ weight,
                    const float* __restrict__ bias,
                    float* __restrict__ out)
{
    extern __shared__ float smem[];
    float* WsBase = smem;                            // [2][KC][WS_STRIDE]
    float* PsBase = smem + 2 * KC * WS_STRIDE;       // [2][KC][PS_STRIDE]

    const int tid = threadIdx.x;
    const int row = tid >> 3;    // 0..15
    const int col = tid & 7;     // 0..7
    const int loc = blockIdx.x;  // (h,w)
    const int h = loc >> 5;
    const int w = loc & 31;

    float acc[8][8];
#pragma unroll
    for (int i = 0; i < 8; i++)
#pragma unroll
        for (int j = 0; j < 8; j++) acc[i][j] = 0.f;

    const float* wg = weight + (size_t)loc * KTOT;

    float4 wreg[8];
    float  preg[16];

    // prime the pipeline: chunk 0 -> buffer 0
    prefetch_tiles(wg, x, 0, h, w, tid, wreg, preg);
    store_tiles(WsBase, PsBase, tid, wreg, preg);

    for (int c = 0; c < NCHUNK; c++) {
        // issue next chunk's global loads BEFORE the barrier -> latency is
        // covered by this chunk's 2048 FFMAs
        if (c + 1 < NCHUNK)
            prefetch_tiles(wg, x, (c + 1) * KC, h, w, tid, wreg, preg);

        __syncthreads();   // buffer (c&1) fully written by all threads

        const float* Ws = WsBase + (c & 1) * KC * WS_STRIDE;
        const float* Ps = PsBase + (c & 1) * KC * PS_STRIDE;

#pragma unroll 8
        for (int kk = 0; kk < KC; kk++) {
            float wv[8], pv[8];
            *(float4*)&wv[0] = *(const float4*)&Ws[kk * WS_STRIDE + row * 4];
            *(float4*)&wv[4] = *(const float4*)&Ws[kk * WS_STRIDE + 64 + row * 4];
            *(float4*)&pv[0] = *(const float4*)&Ps[kk * PS_STRIDE + col * 4];
            *(float4*)&pv[4] = *(const float4*)&Ps[kk * PS_STRIDE + 32 + col * 4];
#pragma unroll
            for (int io = 0; io < 8; io++)
#pragma unroll
                for (int ib = 0; ib < 8; ib++)
                    acc[io][ib] += wv[io] * pv[ib];
        }

        // commit prefetched regs into the OTHER buffer (no barrier needed:
        // the barrier at the top of the next iteration orders reads/writes)
        if (c + 1 < NCHUNK) {
            float* Wn = WsBase + ((c + 1) & 1) * KC * WS_STRIDE;
            float* Pn = PsBase + ((c + 1) & 1) * KC * PS_STRIDE;
            store_tiles(Wn, Pn, tid, wreg, preg);
        }
    }

    // epilogue: out[b][o][h][w]
#pragma unroll
    for (int io = 0; io < 8; io++) {
        int o = (io < 4) ? (row * 4 + io) : (64 + row * 4 + (io - 4));
        float bv = bias[(o << 10) + loc];
#pragma unroll
        for (int ib = 0; ib < 8; ib++) {
            int b = (ib < 4) ? (col * 4 + ib) : (32 + col * 4 + (ib - 4));
            out[((b * COUT + o) << 10) + loc] = acc[io][ib] + bv;
        }
    }
}

extern "C" void kernel_launch(void* const* d_in, const int* in_sizes, int n_in,
                              void* d_out, int out_size) {
    const float* x      = (const float*)d_in[0];
    const float* weight = (const float*)d_in[1];
    const float* bias   = (const float*)d_in[2];
    float* out = (float*)d_out;
    cudaFuncSetAttribute(local2d_kernel,
                         cudaFuncAttributeMaxDynamicSharedMemorySize, SMEM_BYTES);
    local2d_kernel<<<1024, 128, SMEM_BYTES>>>(x, weight, bias, out);
}

// round 7
// speedup vs baseline: 2.1950x; 2.0339x over previous
#include <cuda_runtime.h>
#include <cstdint>

// Local2d as 1024 GEMMs C[o,b] = sum_k W[o,k]*P[b,k], M=128, N=64, K=576.
// Tensor path: legacy mma.sync.m16n8k8 tf32 (compute_103-safe; tcgen05 is
// 'a'-gated and the harness builds PTX at compute_103).
// Kernel1: one location per CTA, 4 warps (warp tile 32x64), K-chunks of 32,
//   double-buffered smem + register prefetch. Writes scratch[loc][o][b]
//   fully coalesced.
// Kernel2: 32x32 tiled transpose scratch -> out[b][o][loc], fused bias add.

#define KTOT  576
#define KC    32
#define NCH   18
#define APAD  36                       // [o][k] row pad: bank = 4g+tig, conflict-free
#define A_BUF_WORDS (128 * APAD)       // 4608
#define B_BUF_WORDS 2048               // packed fragment layout
#define AOFF(b) ((b) * A_BUF_WORDS)
#define BOFF(b) (2 * A_BUF_WORDS + (b) * B_BUF_WORDS)
#define SMEM_BYTES ((2 * A_BUF_WORDS + 2 * B_BUF_WORDS) * 4)

__device__ float g_scratch[1024 * 128 * 64];   // [loc][o][b] = 32MB

__device__ __forceinline__ uint32_t f2tf32(float f) {
    uint32_t u;
    asm("cvt.rna.tf32.f32 %0, %1;" : "=r"(u) : "f"(f));
    return u;
}

__device__ __forceinline__ void mma_tf32(float* d, const uint32_t* a, uint32_t b0, uint32_t b1) {
    asm volatile(
        "mma.sync.aligned.m16n8k8.row.col.f32.tf32.tf32.f32 "
        "{%0,%1,%2,%3}, {%4,%5,%6,%7}, {%8,%9}, {%0,%1,%2,%3};"
        : "+f"(d[0]), "+f"(d[1]), "+f"(d[2]), "+f"(d[3])
        : "r"(a[0]), "r"(a[1]), "r"(a[2]), "r"(a[3]), "r"(b0), "r"(b1));
}

// global loads for chunk c (k0 = c*32) into registers
__device__ __forceinline__ void prefetch(int c, int loc, int h, int w, int tid,
                                         const float* __restrict__ weight,
                                         const float* __restrict__ x,
                                         float4 (&wr)[8], float (&pr)[16]) {
    const int k0 = c * KC;
    const float* wg = weight + (size_t)loc * KTOT;
#pragma unroll
    for (int j = 0; j < 8; j++) {                 // W: 128o x 32k, coalesced LDG.128
        int idx = j * 128 + tid;
        int o   = idx >> 3;
        int q   = idx & 7;
        wr[j] = *(const float4*)(wg + (size_t)o * (1024 * KTOT) + k0 + q * 4);
    }
    const int kkl = tid & 31;
#pragma unroll
    for (int j = 0; j < 16; j++) {                // P: 64b x 32k gather (L2-resident x)
        int b  = j * 4 + (tid >> 5);
        int kg = k0 + kkl;
        int ci = kg / 9;
        int r  = kg - ci * 9;
        int dh = r / 3;
        int dw = r - dh * 3;
        int hh = h - 1 + dh;
        int ww = w - 1 + dw;
        float v = 0.f;
        if ((unsigned)hh < 32u && (unsigned)ww < 32u)
            v = x[(((b << 6) + ci) << 10) + (hh << 5) + ww];
        pr[j] = v;
    }
}

__device__ __forceinline__ void store_chunk(uint32_t* sm, int buf, int tid,
                                            const float4 (&wr)[8], const float (&pr)[16]) {
    // A: [o][APAD] rows, STS.128, conflict-free (bank-group = (9d+q)&7 distinct)
#pragma unroll
    for (int j = 0; j < 8; j++) {
        int idx = j * 128 + tid;
        int o   = idx >> 3;
        int q   = idx & 7;
        uint4 v;
        v.x = f2tf32(wr[j].x); v.y = f2tf32(wr[j].y);
        v.z = f2tf32(wr[j].z); v.w = f2tf32(wr[j].w);
        *(uint4*)(sm + AOFF(buf) + o * APAD + q * 4) = v;
    }
    // B: packed fragment order [ks][nt][lane][half] ^ (ks<<3): conflict-free STS.32
    const int kk = tid & 31;
    const int ks = kk >> 3, klo = kk & 7;
    const int t2 = klo & 3, hf = klo >> 2;
#pragma unroll
    for (int j = 0; j < 16; j++) {
        int b  = j * 4 + (tid >> 5);
        int nt = b >> 3, g2 = b & 7;
        int word = (ks * 512 + nt * 64 + (g2 * 4 + t2) * 2 + hf) ^ (ks << 3);
        sm[BOFF(buf) + word] = f2tf32(pr[j]);
    }
}

__global__ __launch_bounds__(128)
void local2d_mma_kernel(const float* __restrict__ x,
                        const float* __restrict__ weight)
{
    extern __shared__ uint32_t sm[];
    const int tid  = threadIdx.x;
    const int warp = tid >> 5;
    const int lane = tid & 31;
    const int g    = lane >> 2;       // fragment group 0..7
    const int t    = lane & 3;        // thread-in-group 0..3
    const int wo   = warp * 32;       // warp's M base
    const int loc  = blockIdx.x;
    const int h    = loc >> 5, w = loc & 31;

    float d[2][8][4];                 // [mt][nt][frag]
#pragma unroll
    for (int i = 0; i < 2; i++)
#pragma unroll
        for (int j = 0; j < 8; j++)
#pragma unroll
            for (int e = 0; e < 4; e++) d[i][j][e] = 0.f;

    float4 wr[8];
    float  pr[16];

    prefetch(0, loc, h, w, tid, weight, x, wr, pr);
    store_chunk(sm, 0, tid, wr, pr);

#pragma unroll 1
    for (int c = 0; c < NCH; c++) {
        if (c + 1 < NCH) prefetch(c + 1, loc, h, w, tid, weight, x, wr, pr);
        __syncthreads();              // buffer (c&1) visible to all

        const uint32_t* Ab = sm + AOFF(c & 1);
        const uint32_t* Bb = sm + BOFF(c & 1);
        const uint32_t* Ar = Ab + (wo + g) * APAD;

#pragma unroll
        for (int ks = 0; ks < 4; ks++) {
            uint32_t a[2][4];
#pragma unroll
            for (int mt = 0; mt < 2; mt++) {
                const uint32_t* ap = Ar + mt * (16 * APAD) + ks * 8 + t;
                a[mt][0] = ap[0];
                a[mt][1] = ap[8 * APAD];
                a[mt][2] = ap[4];
                a[mt][3] = ap[8 * APAD + 4];
            }
#pragma unroll
            for (int nt = 0; nt < 8; nt++) {
                int word = (ks * 512 + nt * 64 + lane * 2) ^ (ks << 3);
                uint2 bb = *(const uint2*)(Bb + word);
                mma_tf32(d[0][nt], a[0], bb.x, bb.y);
                mma_tf32(d[1][nt], a[1], bb.x, bb.y);
            }
        }

        if (c + 1 < NCH) store_chunk(sm, (c + 1) & 1, tid, wr, pr);
    }

    // epilogue -> scratch[loc][o][b], coalesced 32B runs
    float* sc = g_scratch + (size_t)loc * (128 * 64);
#pragma unroll
    for (int mt = 0; mt < 2; mt++)
#pragma unroll
        for (int ab = 0; ab < 2; ab++) {
            int r = wo + mt * 16 + ab * 8 + g;
#pragma unroll
            for (int nt = 0; nt < 8; nt++) {
                int cb = nt * 8 + 2 * t;
                float2 v = make_float2(d[mt][nt][ab * 2 + 0], d[mt][nt][ab * 2 + 1]);
                *(float2*)(sc + r * 64 + cb) = v;
            }
        }
}

// scratch[loc][o][b] -> out[b][o][loc] (+bias[o][loc]) via 32(loc)x64(b) tiles
__global__ __launch_bounds__(256)
void transpose_bias_kernel(const float* __restrict__ bias,
                           float* __restrict__ out)
{
    __shared__ float s2[32][65];
    const int loc0 = blockIdx.x * 32;
    const int o    = blockIdx.y;
    const int tid  = threadIdx.x;

    {   // load: rows = loc, cols = b (coalesced 128B per half-row)
        const int c = tid & 63, r0 = tid >> 6;
#pragma unroll
        for (int i = 0; i < 8; i++) {
            int r = i * 4 + r0;
            s2[r][c] = g_scratch[((size_t)(loc0 + r) * 128 + o) * 64 + c];
        }
    }
    __syncthreads();

    const int lc = tid & 31;
    const int b0 = tid >> 5;         // 0..7
    const float bv = bias[(o << 10) + loc0 + lc];
#pragma unroll
    for (int i = 0; i < 8; i++) {
        int b = i * 8 + b0;
        out[((size_t)(b * 128 + o) << 10) + loc0 + lc] = s2[lc][b] + bv;
    }
}

extern "C" void kernel_launch(void* const* d_in, const int* in_sizes, int n_in,
                              void* d_out, int out_size) {
    const float* x      = (const float*)d_in[0];
    const float* weight = (const float*)d_in[1];
    const float* bias   = (const float*)d_in[2];
    float* out = (float*)d_out;

    cudaFuncSetAttribute(local2d_mma_kernel,
                         cudaFuncAttributeMaxDynamicSharedMemorySize, SMEM_BYTES);
    local2d_mma_kernel<<<1024, 128, SMEM_BYTES>>>(x, weight);
    transpose_bias_kernel<<<dim3(32, 128), 256>>>(bias, out);
}